// round 1
// baseline (speedup 1.0000x reference)
#include <cuda_runtime.h>
#include <cstdint>

// ---------------- problem constants ----------------
#define NN   65536      // base nodes
#define MM   65536      // local nodes
#define HH   128        // hidden / feature dim
#define BB   64         // groups
#define OUTD 2
#define ALPHA 0.9f

// ---------------- device scratch (no runtime allocation allowed) ----------------
__device__ float g_base_x  [(size_t)NN * HH];
__device__ float g_base_agg[(size_t)NN * HH];
__device__ float g_local_x [(size_t)MM * HH];
__device__ float g_local_agg[(size_t)MM * HH];
__device__ float g_sub[BB * HH];
__device__ float g_cnt[BB];

// ---------------- GEMM: C[R x128] = relu(A[R x128] @ W[128x128] + bias) ----------------
// block: 256 threads, 128 rows x 128 cols per block, 8x8 microtile per thread.
// smem: As transposed [k][row] padded to 132 floats/row; Ws [k][col] dense.
#define AS_LD 132
#define GEMM_SMEM ((128 * AS_LD + 128 * 128) * sizeof(float))

__global__ void __launch_bounds__(256, 1)
gemm128_bias_relu(const float* __restrict__ A,
                  const float* __restrict__ W,
                  const float* __restrict__ bias,
                  float* __restrict__ C)
{
    extern __shared__ float smem[];
    float* As = smem;                 // [128][AS_LD]  As[k][row]
    float* Ws = smem + 128 * AS_LD;   // [128][128]    Ws[k][col]

    const int tid  = threadIdx.x;
    const int row0 = blockIdx.x * 128;

    // load W (16384 floats) -> Ws, 16 float4 per thread, coalesced
    {
        const float4* W4  = (const float4*)W;
        float4*       Ws4 = (float4*)Ws;
        #pragma unroll
        for (int i = 0; i < 16; i++) Ws4[tid + 256 * i] = W4[tid + 256 * i];
    }
    // load A tile transposed into As[k][row]
    {
        const float4* A4 = (const float4*)(A + (size_t)row0 * HH);
        #pragma unroll
        for (int i = 0; i < 16; i++) {
            int idx = tid + 256 * i;      // = r*32 + k4
            int r   = idx >> 5;
            int k4  = idx & 31;
            float4 v = A4[idx];
            As[(4 * k4 + 0) * AS_LD + r] = v.x;
            As[(4 * k4 + 1) * AS_LD + r] = v.y;
            As[(4 * k4 + 2) * AS_LD + r] = v.z;
            As[(4 * k4 + 3) * AS_LD + r] = v.w;
        }
    }
    __syncthreads();

    const int tr = (tid >> 4) * 8;   // row offset in tile (0..120)
    const int tc = (tid & 15) * 8;   // col offset in tile (0..120)

    float acc[8][8];
    #pragma unroll
    for (int i = 0; i < 8; i++)
        #pragma unroll
        for (int j = 0; j < 8; j++) acc[i][j] = 0.f;

    #pragma unroll 4
    for (int k = 0; k < 128; k++) {
        float a[8], w[8];
        *(float4*)&a[0] = *(const float4*)&As[k * AS_LD + tr];
        *(float4*)&a[4] = *(const float4*)&As[k * AS_LD + tr + 4];
        *(float4*)&w[0] = *(const float4*)&Ws[k * 128 + tc];
        *(float4*)&w[4] = *(const float4*)&Ws[k * 128 + tc + 4];
        #pragma unroll
        for (int i = 0; i < 8; i++)
            #pragma unroll
            for (int j = 0; j < 8; j++) acc[i][j] = fmaf(a[i], w[j], acc[i][j]);
    }

    float bv[8];
    *(float4*)&bv[0] = *(const float4*)&bias[tc];
    *(float4*)&bv[4] = *(const float4*)&bias[tc + 4];

    #pragma unroll
    for (int i = 0; i < 8; i++) {
        float* cp = &C[(size_t)(row0 + tr + i) * HH + tc];
        float4 v0, v1;
        v0.x = fmaxf(acc[i][0] + bv[0], 0.f);
        v0.y = fmaxf(acc[i][1] + bv[1], 0.f);
        v0.z = fmaxf(acc[i][2] + bv[2], 0.f);
        v0.w = fmaxf(acc[i][3] + bv[3], 0.f);
        v1.x = fmaxf(acc[i][4] + bv[4], 0.f);
        v1.y = fmaxf(acc[i][5] + bv[5], 0.f);
        v1.z = fmaxf(acc[i][6] + bv[6], 0.f);
        v1.w = fmaxf(acc[i][7] + bv[7], 0.f);
        ((float4*)cp)[0] = v0;
        ((float4*)cp)[1] = v1;
    }
}

// ---------------- SpMM scatter: Y[dst] += w * X[src], warp per edge ----------------
__global__ void spmm_atomic(const float* __restrict__ X,
                            const int* __restrict__ src,
                            const int* __restrict__ dst,
                            const float* __restrict__ wgt,
                            float* __restrict__ Y, int E)
{
    const int lane   = threadIdx.x & 31;
    const int warp   = (blockIdx.x * blockDim.x + threadIdx.x) >> 5;
    const int nwarps = (gridDim.x * blockDim.x) >> 5;
    for (int e = warp; e < E; e += nwarps) {
        int   s = src[e];
        int   d = dst[e];
        float w = wgt[e];
        float4 v = *(const float4*)&X[(size_t)s * HH + lane * 4];
        v.x *= w; v.y *= w; v.z *= w; v.w *= w;
        float* p = &Y[(size_t)d * HH + lane * 4];
        asm volatile("red.global.add.v4.f32 [%0], {%1, %2, %3, %4};"
                     :: "l"(p), "f"(v.x), "f"(v.y), "f"(v.z), "f"(v.w)
                     : "memory");
    }
}

// ---------------- mix: agg = ALPHA*agg + (1-ALPHA)*base_x[copy2orig] ----------------
__global__ void mix_kernel(float* __restrict__ agg,
                           const float* __restrict__ bx,
                           const int* __restrict__ c2o, int M)
{
    int i = blockIdx.x * blockDim.x + threadIdx.x;   // float4 index
    int total = M * (HH / 4);
    if (i >= total) return;
    int node = i >> 5;          // HH/4 = 32 float4 per node
    int f4   = i & 31;
    int o = c2o[node];
    float4 a = ((float4*)agg)[i];
    float4 b = *(const float4*)&bx[(size_t)o * HH + f4 * 4];
    a.x = ALPHA * a.x + (1.0f - ALPHA) * b.x;
    a.y = ALPHA * a.y + (1.0f - ALPHA) * b.y;
    a.z = ALPHA * a.z + (1.0f - ALPHA) * b.z;
    a.w = ALPHA * a.w + (1.0f - ALPHA) * b.w;
    ((float4*)agg)[i] = a;
}

// ---------------- pooling: two-stage segment-sum into g_sub / g_cnt ----------------
__global__ void pool_kernel(const float* __restrict__ lx,
                            const int* __restrict__ midx,
                            const int* __restrict__ mgid,
                            float* __restrict__ gsub,
                            float* __restrict__ gcnt,
                            int K, int entries_per_block)
{
    __shared__ float acc[BB * HH];   // 32 KB
    __shared__ float cnt[BB];
    const int tid = threadIdx.x;
    for (int i = tid; i < BB * HH; i += blockDim.x) acc[i] = 0.f;
    if (tid < BB) cnt[tid] = 0.f;
    __syncthreads();

    const int warp = tid >> 5;
    const int lane = tid & 31;
    const int base = blockIdx.x * entries_per_block;
    const int end  = min(base + entries_per_block, K);
    for (int k = base + warp; k < end; k += (int)(blockDim.x >> 5)) {
        int idx = midx[k];
        int g   = mgid[k];
        float4 v = *(const float4*)&lx[(size_t)idx * HH + lane * 4];
        atomicAdd(&acc[g * HH + lane * 4 + 0], v.x);
        atomicAdd(&acc[g * HH + lane * 4 + 1], v.y);
        atomicAdd(&acc[g * HH + lane * 4 + 2], v.z);
        atomicAdd(&acc[g * HH + lane * 4 + 3], v.w);
        if (lane == 0) atomicAdd(&cnt[g], 1.f);
    }
    __syncthreads();

    for (int i = tid; i < BB * HH; i += blockDim.x)
        if (acc[i] != 0.f) atomicAdd(&gsub[i], acc[i]);
    if (tid < BB && cnt[tid] != 0.f) atomicAdd(&gcnt[tid], cnt[tid]);
}

// ---------------- final: out[b][o] = (sub[b]/max(cnt,1)) @ Wp + bp ----------------
__global__ void final_kernel(const float* __restrict__ gsub,
                             const float* __restrict__ gcnt,
                             const float* __restrict__ Wp,
                             const float* __restrict__ bp,
                             float* __restrict__ out)
{
    int t = threadIdx.x;                 // 0..127
    if (t >= BB * OUTD) return;
    int b = t >> 1, o = t & 1;
    float c = fmaxf(gcnt[b], 1.f);
    float s = 0.f;
    #pragma unroll 8
    for (int h = 0; h < HH; h++) s = fmaf(gsub[b * HH + h], Wp[h * OUTD + o], s);
    out[t] = s / c + bp[o];
}

// ---------------- host orchestration ----------------
extern "C" void kernel_launch(void* const* d_in, const int* in_sizes, int n_in,
                              void* d_out, int out_size)
{
    const float* x    = (const float*)d_in[0];
    const int*   ei   = (const int*)  d_in[1];
    const float* ew   = (const float*)d_in[2];
    const float* lx0  = (const float*)d_in[3];
    const int*   c2o  = (const int*)  d_in[4];
    const int*   lei  = (const int*)  d_in[5];
    const float* lev  = (const float*)d_in[6];
    const int*   midx = (const int*)  d_in[7];
    const int*   mgid = (const int*)  d_in[8];
    // d_in[9] = B (scalar) -- fixed at 64
    const float* Wb    = (const float*)d_in[10];
    const float* bb    = (const float*)d_in[11];
    const float* Wl    = (const float*)d_in[12];
    const float* bl    = (const float*)d_in[13];
    const float* Wbase = (const float*)d_in[14];
    const float* bbase = (const float*)d_in[15];
    const float* Wloc  = (const float*)d_in[16];
    const float* bloc  = (const float*)d_in[17];
    const float* Wp    = (const float*)d_in[18];
    const float* bp    = (const float*)d_in[19];
    float* out = (float*)d_out;

    const int N  = in_sizes[0] / HH;
    const int M  = in_sizes[3] / HH;
    const int E  = in_sizes[1] / 2;
    const int EL = in_sizes[5] / 2;
    const int K  = in_sizes[7];
    const int L  = in_sizes[14] / (HH * HH);

    float *base_x, *base_agg, *local_x, *local_agg, *sub, *cntp;
    cudaGetSymbolAddress((void**)&base_x,   g_base_x);
    cudaGetSymbolAddress((void**)&base_agg, g_base_agg);
    cudaGetSymbolAddress((void**)&local_x,  g_local_x);
    cudaGetSymbolAddress((void**)&local_agg,g_local_agg);
    cudaGetSymbolAddress((void**)&sub,      g_sub);
    cudaGetSymbolAddress((void**)&cntp,     g_cnt);

    cudaFuncSetAttribute(gemm128_bias_relu,
                         cudaFuncAttributeMaxDynamicSharedMemorySize,
                         (int)GEMM_SMEM);

    const int gemm_blocks_N = N / 128;
    const int gemm_blocks_M = M / 128;

    // input projections
    gemm128_bias_relu<<<gemm_blocks_N, 256, GEMM_SMEM>>>(x,   Wb, bb, base_x);
    gemm128_bias_relu<<<gemm_blocks_M, 256, GEMM_SMEM>>>(lx0, Wl, bl, local_x);

    const int spmm_blocks = 4096;
    const int mix_blocks  = (M * (HH / 4) + 255) / 256;

    for (int l = 0; l < L; l++) {
        // base graph propagation
        cudaMemsetAsync(base_agg, 0, (size_t)N * HH * sizeof(float));
        spmm_atomic<<<spmm_blocks, 256>>>(base_x, ei, ei + E, ew, base_agg, E);
        gemm128_bias_relu<<<gemm_blocks_N, 256, GEMM_SMEM>>>(
            base_agg, Wbase + (size_t)l * HH * HH, bbase + (size_t)l * HH, base_x);

        // local union-graph propagation + alpha mix
        cudaMemsetAsync(local_agg, 0, (size_t)M * HH * sizeof(float));
        spmm_atomic<<<spmm_blocks, 256>>>(local_x, lei, lei + EL, lev, local_agg, EL);
        mix_kernel<<<mix_blocks, 256>>>(local_agg, base_x, c2o, M);
        gemm128_bias_relu<<<gemm_blocks_M, 256, GEMM_SMEM>>>(
            local_agg, Wloc + (size_t)l * HH * HH, bloc + (size_t)l * HH, local_x);
    }

    // scatter-mean pooling + final projection
    cudaMemsetAsync(sub,  0, BB * HH * sizeof(float));
    cudaMemsetAsync(cntp, 0, BB * sizeof(float));
    const int pool_blocks = 128;
    const int entries_per_block = (K + pool_blocks - 1) / pool_blocks;
    pool_kernel<<<pool_blocks, 256>>>(local_x, midx, mgid, sub, cntp, K, entries_per_block);
    final_kernel<<<1, 128>>>(sub, cntp, Wp, bp, out);
}